// round 10
// baseline (speedup 1.0000x reference)
#include <cuda_runtime.h>
#include <cstdint>

// ---------------- problem dims ----------------
#define TT   512
#define BB   64
#define DIN  512
#define HH   1024
#define G3   3072
#define DOUT 512
#define TBR  (TT*BB)     // 32768 rows

#define NCTA 128         // persistent kernel grid
#define JSL  8           // hidden columns per CTA (128*8 = 1024)

// ---------------- device scratch (no allocations allowed) ----------------
__device__ float g_xg[(size_t)TBR * G3];   // gate pre-activations (reused as LN output)
__device__ float g_y [(size_t)TBR * HH];   // layer output sequence
__device__ float g_h [2 * BB * HH];        // ping-pong hidden state
__device__ unsigned g_flag[8 * 32];        // per-chunk producer counters (128B padded)

// ---------------- helpers ----------------
__device__ __forceinline__ unsigned f2tf(float x) {
    unsigned r;
    asm("cvt.rna.tf32.f32 %0, %1;" : "=r"(r) : "f"(x));
    return r;
}

__device__ __forceinline__ void mma8(float* c, const unsigned* a, const unsigned* b) {
    asm volatile(
        "mma.sync.aligned.m16n8k8.row.col.f32.tf32.tf32.f32 "
        "{%0,%1,%2,%3},{%4,%5,%6,%7},{%8,%9},{%0,%1,%2,%3};"
        : "+f"(c[0]), "+f"(c[1]), "+f"(c[2]), "+f"(c[3])
        : "r"(a[0]), "r"(a[1]), "r"(a[2]), "r"(a[3]), "r"(b[0]), "r"(b[1]));
}

__device__ __forceinline__ float sigmoid_fast(float x) {
    return __fdividef(1.0f, 1.0f + __expf(-x));
}

__device__ __forceinline__ float tanh_fast(float x) {
    x = fminf(fmaxf(x, -15.0f), 15.0f);
    float t = __expf(2.0f * x);
    return __fdividef(t - 1.0f, t + 1.0f);
}

// =====================================================================
// Generic GEMM: C[M,N] = A[M,K] * B[N,K]^T + bias[N]   (tf32 tensor cores)
// CTA tile 128x128, BK=32, 128 threads, warp grid 2x2 (warp tile 64x64).
// 2-stage cp.async double buffer (80 KB), 2 CTAs/SM. Bigger warp tiles
// cut fragment-LDS bytes per mma 1.5x so the smem crossbar no longer
// co-binds with the tensor pipe. Requires M,N%128==0, K%64==0.
// =====================================================================
#define GST 40           // smem row stride in floats (mod 32 == 8, conflict-free)

__global__ __launch_bounds__(128, 2)
void gemm_tn(const float* __restrict__ A, const float* __restrict__ B,
             const float* __restrict__ bias, float* __restrict__ C,
             int M, int N, int K)
{
    extern __shared__ float gsm[];
    float* As = gsm;                         // [2][128][GST]
    float* Bs = gsm + 2 * 128 * GST;         // [2][128][GST]

    const int tid  = threadIdx.x;
    const int lane = tid & 31;
    const int warp = tid >> 5;
    const int wm   = (warp >> 1) * 64;   // warp grid 2 (M) x 2 (N)
    const int wn   = (warp & 1) * 64;
    const int gq   = lane >> 2;
    const int t4   = lane & 3;

    const int m0 = blockIdx.y * 128;
    const int n0 = blockIdx.x * 128;

    const int ld_row = tid >> 3;          // 0..15 (x8 strided covers 128 rows)
    const int ld_c4  = (tid & 7) * 4;

    const int nk = K / 32;

    auto issue = [&](int slot, int i) {
        const int kt = i * 32;
#pragma unroll
        for (int r = 0; r < 8; ++r) {
            int row = ld_row + 16 * r;
            const float* srcA = &A[(size_t)(m0 + row) * K + kt + ld_c4];
            const float* srcB = &B[(size_t)(n0 + row) * K + kt + ld_c4];
            unsigned dA = (unsigned)__cvta_generic_to_shared(
                &As[(slot * 128 + row) * GST + ld_c4]);
            unsigned dB = (unsigned)__cvta_generic_to_shared(
                &Bs[(slot * 128 + row) * GST + ld_c4]);
            asm volatile("cp.async.cg.shared.global [%0], [%1], 16;" :: "r"(dA), "l"(srcA));
            asm volatile("cp.async.cg.shared.global [%0], [%1], 16;" :: "r"(dB), "l"(srcB));
        }
        asm volatile("cp.async.commit_group;" ::: "memory");
    };

    float c[4][8][4];
#pragma unroll
    for (int i = 0; i < 4; ++i)
#pragma unroll
        for (int j = 0; j < 8; ++j)
#pragma unroll
            for (int r = 0; r < 4; ++r) c[i][j][r] = 0.0f;

    issue(0, 0);
    issue(1, 1);

    for (int i = 0; i < nk; ++i) {
        if (i + 1 < nk) asm volatile("cp.async.wait_group 1;" ::: "memory");
        else            asm volatile("cp.async.wait_group 0;" ::: "memory");
        __syncthreads();

        const float* as = As + (i & 1) * 128 * GST;
        const float* bs = Bs + (i & 1) * 128 * GST;
#pragma unroll
        for (int kk = 0; kk < 4; ++kk) {
            const int cc = kk * 8 + 2 * t4;
            unsigned a[4][4], b[8][2];
#pragma unroll
            for (int mi = 0; mi < 4; ++mi) {
                int r0 = wm + mi * 16 + gq;
                float2 x0 = *(const float2*)&as[r0 * GST + cc];
                float2 x1 = *(const float2*)&as[(r0 + 8) * GST + cc];
                a[mi][0] = f2tf(x0.x); a[mi][1] = f2tf(x1.x);
                a[mi][2] = f2tf(x0.y); a[mi][3] = f2tf(x1.y);
            }
#pragma unroll
            for (int ni = 0; ni < 8; ++ni) {
                float2 z = *(const float2*)&bs[(wn + ni * 8 + gq) * GST + cc];
                b[ni][0] = f2tf(z.x); b[ni][1] = f2tf(z.y);
            }
#pragma unroll
            for (int mi = 0; mi < 4; ++mi)
#pragma unroll
                for (int ni = 0; ni < 8; ++ni)
                    mma8(c[mi][ni], a[mi], b[ni]);
        }

        __syncthreads();
        if (i + 2 < nk) issue(i & 1, i + 2);
    }

    // epilogue: C = acc + bias
#pragma unroll
    for (int mi = 0; mi < 4; ++mi) {
#pragma unroll
        for (int ni = 0; ni < 8; ++ni) {
            int row = m0 + wm + mi * 16 + gq;
            int col = n0 + wn + ni * 8 + 2 * t4;
            float b0 = bias[col], b1 = bias[col + 1];
            float2 v0 = make_float2(c[mi][ni][0] + b0, c[mi][ni][1] + b1);
            float2 v1 = make_float2(c[mi][ni][2] + b0, c[mi][ni][3] + b1);
            *(float2*)&C[(size_t)row * N + col]       = v0;
            *(float2*)&C[(size_t)(row + 8) * N + col] = v1;
        }
    }
}

// =====================================================================
// Persistent GRU layer kernel — direct-L2 A operands.
// grid = NCTA (128), 128 threads (4 warps, all consumers). CTA b owns
// hidden cols [b*8, b*8+8). Weight slice (24 x 1024) smem-resident tf32.
// Per step: each warp streams its 16 h rows DIRECTLY from L2 into
// registers as mma fragments (double-banked 16-kk prefetch) — no smem
// staging, no producers, no intra-step __syncthreads.
// Step sync: one release-atomic per CTA; threads 0-7 acquire-poll the
// 8 chunk counters in parallel at step start.
// =====================================================================
#define WSTRIDE 1032

__global__ __launch_bounds__(128, 1)
void gru_layer(const float* __restrict__ w_hh, const float* __restrict__ b_hh)
{
    extern __shared__ unsigned Bs[];                          // [24][WSTRIDE]

    const int tid   = threadIdx.x;
    const int lane  = tid & 31;
    const int warp  = tid >> 5;          // 0..3, all consumers
    const int gq    = lane >> 2;
    const int t4    = lane & 3;
    const int r0    = warp * 16;         // M-tile rows
    const int j0    = blockIdx.x * JSL;
    const int jc    = j0 + 2 * t4;
    const int cj    = j0 >> 7;           // chunk counter owned by this CTA

    // ---- preload weight slice (24 x 1024) as tf32 ----
    for (int e = tid; e < 24 * 256; e += 128) {
        int row = e >> 8;
        int c4  = (e & 255) * 4;
        int gate = row >> 3, jj = row & 7;
        float4 v = *(const float4*)&w_hh[(size_t)(gate * HH + j0 + jj) * HH + c4];
        uint4 u; u.x = f2tf(v.x); u.y = f2tf(v.y); u.z = f2tf(v.z); u.w = f2tf(v.w);
        *(uint4*)&Bs[row * WSTRIDE + c4] = u;
    }
    __syncthreads();

    // ---- hoist b_hh ----
    float2 bhr = *(const float2*)&b_hh[jc];
    float2 bhz = *(const float2*)&b_hh[HH + jc];
    float2 bhn = *(const float2*)&b_hh[2 * HH + jc];

    for (int t = 0; t < TT; ++t) {
        const float* h_in  = g_h + (size_t)(t & 1) * (BB * HH);
        float*       h_out = g_h + (size_t)((t + 1) & 1) * (BB * HH);
        const float* xg_t  = g_xg + (size_t)t * BB * G3;
        float*       y_t   = g_y  + (size_t)t * BB * HH;

        // ---- prefetch xg operands BEFORE the barrier (always ready) ----
        float2 xr0, xz0, xn0, xr1, xz1, xn1;
        {
            const float* xp0 = xg_t + (size_t)(r0 + gq) * G3 + jc;
            const float* xp1 = xg_t + (size_t)(r0 + gq + 8) * G3 + jc;
            xr0 = *(const float2*)(xp0);
            xz0 = *(const float2*)(xp0 + HH);
            xn0 = *(const float2*)(xp0 + 2 * HH);
            xr1 = *(const float2*)(xp1);
            xz1 = *(const float2*)(xp1 + HH);
            xn1 = *(const float2*)(xp1 + 2 * HH);
        }

        // ---- step barrier: wait for all 8 chunk groups of step t-1 ----
        if (tid < 8) {
            const unsigned tgt = 16u * (unsigned)t;
            const unsigned* fp = &g_flag[tid * 32];
            unsigned v;
            do {
                asm volatile("ld.acquire.gpu.global.u32 %0, [%1];" : "=r"(v) : "l"(fp));
            } while (v < tgt);
        }
        __syncthreads();

        // h-side operands
        const float* ha = h_in + (r0 + gq) * HH + 2 * t4;   // A rows (this thread)
        const float* hb = ha + 8 * HH;
        float2 hold0 = *(const float2*)&h_in[(r0 + gq) * HH + jc];
        float2 hold1 = *(const float2*)&h_in[(r0 + gq + 8) * HH + jc];

        // ---- hg = h_in * w_sliceT : A direct from L2, double-banked ----
        float2 pa[2][16], pb[2][16];
#pragma unroll
        for (int j = 0; j < 16; ++j) {
            pa[0][j] = *(const float2*)(ha + j * 8);
            pb[0][j] = *(const float2*)(hb + j * 8);
        }

        float acc[3][4];
#pragma unroll
        for (int ni = 0; ni < 3; ++ni)
#pragma unroll
            for (int r = 0; r < 4; ++r) acc[ni][r] = 0.0f;

        for (int c = 0; c < 8; ++c) {              // 8 chunks x 16 kk = 128 kk
            const int cur = c & 1, nxt = cur ^ 1;
            if (c < 7) {
                const float* ha2 = ha + (c + 1) * 128;   // 16 kk * 8 floats
                const float* hb2 = hb + (c + 1) * 128;
#pragma unroll
                for (int j = 0; j < 16; ++j) {
                    pa[nxt][j] = *(const float2*)(ha2 + j * 8);
                    pb[nxt][j] = *(const float2*)(hb2 + j * 8);
                }
            }
#pragma unroll
            for (int j = 0; j < 16; ++j) {
                const int col = (c * 16 + j) * 8 + 2 * t4;
                unsigned a[4];
                a[0] = f2tf(pa[cur][j].x); a[1] = f2tf(pb[cur][j].x);
                a[2] = f2tf(pa[cur][j].y); a[3] = f2tf(pb[cur][j].y);
#pragma unroll
                for (int ni = 0; ni < 3; ++ni) {
                    uint2 bb = *(const uint2*)&Bs[(ni * 8 + gq) * WSTRIDE + col];
                    unsigned br[2] = { bb.x, bb.y };
                    mma8(acc[ni], a, br);
                }
            }
        }

        // ---- fused gate epilogue (accumulators complete; no reduction) ----
        {
            float r00 = sigmoid_fast(xr0.x + acc[0][0] + bhr.x);
            float r01 = sigmoid_fast(xr0.y + acc[0][1] + bhr.y);
            float r10 = sigmoid_fast(xr1.x + acc[0][2] + bhr.x);
            float r11 = sigmoid_fast(xr1.y + acc[0][3] + bhr.y);
            float z00 = sigmoid_fast(xz0.x + acc[1][0] + bhz.x);
            float z01 = sigmoid_fast(xz0.y + acc[1][1] + bhz.y);
            float z10 = sigmoid_fast(xz1.x + acc[1][2] + bhz.x);
            float z11 = sigmoid_fast(xz1.y + acc[1][3] + bhz.y);
            float n00 = tanh_fast(xn0.x + r00 * (acc[2][0] + bhn.x));
            float n01 = tanh_fast(xn0.y + r01 * (acc[2][1] + bhn.y));
            float n10 = tanh_fast(xn1.x + r10 * (acc[2][2] + bhn.x));
            float n11 = tanh_fast(xn1.y + r11 * (acc[2][3] + bhn.y));

            float2 o0 = make_float2((1.f - z00) * n00 + z00 * hold0.x,
                                    (1.f - z01) * n01 + z01 * hold0.y);
            float2 o1 = make_float2((1.f - z10) * n10 + z10 * hold1.x,
                                    (1.f - z11) * n11 + z11 * hold1.y);
            *(float2*)&h_out[(r0 + gq) * HH + jc]     = o0;
            *(float2*)&h_out[(r0 + gq + 8) * HH + jc] = o1;
            *(float2*)&y_t  [(r0 + gq) * HH + jc]     = o0;
            *(float2*)&y_t  [(r0 + gq + 8) * HH + jc] = o1;
        }

        // ---- publish: syncthreads gives happens-before; one release atomic ----
        __syncthreads();
        if (tid == 0) {
            asm volatile("red.release.gpu.global.add.u32 [%0], %1;"
                         :: "l"(&g_flag[cj * 32]), "r"(1u) : "memory");
        }
    }
}

// =====================================================================
// init hidden state (parity buffer 0) + reset producer flags
// =====================================================================
__global__ void copy_h(const float* __restrict__ src)
{
    int i = blockIdx.x * blockDim.x + threadIdx.x;
    if (i < BB * HH) g_h[i] = src[i];
    if (i < 8 * 32) g_flag[i] = 0;
}

// =====================================================================
// LayerNorm over last dim (1024), one block per row
// =====================================================================
__global__ __launch_bounds__(256)
void ln_kernel(const float* __restrict__ y, const float* __restrict__ gamma,
               const float* __restrict__ beta, float* __restrict__ out)
{
    __shared__ float sh[16];
    const size_t row = blockIdx.x;
    const int tid = threadIdx.x, lane = tid & 31, warp = tid >> 5;

    float4 v = ((const float4*)(y + row * HH))[tid];
    float s = v.x + v.y + v.z + v.w;
    float q = v.x * v.x + v.y * v.y + v.z * v.z + v.w * v.w;
#pragma unroll
    for (int o = 16; o > 0; o >>= 1) {
        s += __shfl_xor_sync(0xffffffffu, s, o);
        q += __shfl_xor_sync(0xffffffffu, q, o);
    }
    if (lane == 0) { sh[warp] = s; sh[8 + warp] = q; }
    __syncthreads();
    if (tid == 0) {
        float S = 0.0f, Q = 0.0f;
#pragma unroll
        for (int i = 0; i < 8; ++i) { S += sh[i]; Q += sh[8 + i]; }
        sh[0] = S; sh[8] = Q;
    }
    __syncthreads();
    const float mu   = sh[0] * (1.0f / HH);
    const float var  = sh[8] * (1.0f / HH) - mu * mu;
    const float rstd = rsqrtf(var + 1e-5f);

    float4 gm = ((const float4*)gamma)[tid];
    float4 bt = ((const float4*)beta)[tid];
    float4 o4;
    o4.x = (v.x - mu) * rstd * gm.x + bt.x;
    o4.y = (v.y - mu) * rstd * gm.y + bt.y;
    o4.z = (v.z - mu) * rstd * gm.z + bt.z;
    o4.w = (v.w - mu) * rstd * gm.w + bt.w;
    ((float4*)(out + row * HH))[tid] = o4;
}

// =====================================================================
// launcher  (8 graph nodes total)
// =====================================================================
extern "C" void kernel_launch(void* const* d_in, const int* in_sizes, int n_in,
                              void* d_out, int out_size)
{
    const float* x      = (const float*)d_in[0];
    const float* h      = (const float*)d_in[1];
    const float* w_ih0  = (const float*)d_in[2];
    const float* w_hh0  = (const float*)d_in[3];
    const float* b_ih0  = (const float*)d_in[4];
    const float* b_hh0  = (const float*)d_in[5];
    const float* w_ih1  = (const float*)d_in[6];
    const float* w_hh1  = (const float*)d_in[7];
    const float* b_ih1  = (const float*)d_in[8];
    const float* b_hh1  = (const float*)d_in[9];
    const float* ln_g   = (const float*)d_in[10];
    const float* ln_b   = (const float*)d_in[11];
    const float* ff_w   = (const float*)d_in[12];
    const float* ff_b   = (const float*)d_in[13];
    float* out = (float*)d_out;

    float* xg = nullptr;
    float* y  = nullptr;
    cudaGetSymbolAddress((void**)&xg, g_xg);
    cudaGetSymbolAddress((void**)&y,  g_y);

    const int smem_gru  = 24 * WSTRIDE * 4;            // 99072 B
    const int smem_gemm = 2 * 2 * 128 * GST * 4;       // 81920 B (2 CTAs/SM)
    cudaFuncSetAttribute(gru_layer, cudaFuncAttributeMaxDynamicSharedMemorySize, smem_gru);
    cudaFuncSetAttribute(gemm_tn,   cudaFuncAttributeMaxDynamicSharedMemorySize, smem_gemm);

    // layer 0: input-side gate projections for all timesteps
    gemm_tn<<<dim3(G3 / 128, TBR / 128), 128, smem_gemm>>>(x, w_ih0, b_ih0, xg, TBR, G3, DIN);

    // layer 0 recurrence (persistent)
    copy_h<<<(BB * HH + 255) / 256, 256>>>(h);
    gru_layer<<<NCTA, 128, smem_gru>>>(w_hh0, b_hh0);

    // layer 1: input-side gate projections
    gemm_tn<<<dim3(G3 / 128, TBR / 128), 128, smem_gemm>>>(y, w_ih1, b_ih1, xg, TBR, G3, HH);

    // layer 1 recurrence (persistent)
    copy_h<<<(BB * HH + 255) / 256, 256>>>(h + BB * HH);
    gru_layer<<<NCTA, 128, smem_gru>>>(w_hh1, b_hh1);

    // LayerNorm (output reuses g_xg buffer)
    ln_kernel<<<TBR, 256>>>(y, ln_g, ln_b, xg);

    // output projection
    gemm_tn<<<dim3(DOUT / 128, TBR / 128), 128, smem_gemm>>>(xg, ff_w, ff_b, out, TBR, DOUT, HH);
}

// round 11
// speedup vs baseline: 1.8575x; 1.8575x over previous
#include <cuda_runtime.h>
#include <cstdint>

// ---------------- problem dims ----------------
#define TT   512
#define BB   64
#define DIN  512
#define HH   1024
#define G3   3072
#define DOUT 512
#define TBR  (TT*BB)     // 32768 rows

#define NCTA 128         // persistent kernel grid
#define JSL  8           // hidden columns per CTA (128*8 = 1024)

// ---------------- device scratch (no allocations allowed) ----------------
__device__ float g_xg[(size_t)TBR * G3];   // gate pre-activations (reused as LN output)
__device__ float g_y [(size_t)TBR * HH];   // layer output sequence
__device__ float g_h [2 * BB * HH];        // ping-pong hidden state
__device__ unsigned g_flag[8 * 32];        // per-chunk producer counters (128B padded)

// ---------------- helpers ----------------
__device__ __forceinline__ unsigned f2tf(float x) {
    unsigned r;
    asm("cvt.rna.tf32.f32 %0, %1;" : "=r"(r) : "f"(x));
    return r;
}

__device__ __forceinline__ void mma8(float* c, const unsigned* a, const unsigned* b) {
    asm volatile(
        "mma.sync.aligned.m16n8k8.row.col.f32.tf32.tf32.f32 "
        "{%0,%1,%2,%3},{%4,%5,%6,%7},{%8,%9},{%0,%1,%2,%3};"
        : "+f"(c[0]), "+f"(c[1]), "+f"(c[2]), "+f"(c[3])
        : "r"(a[0]), "r"(a[1]), "r"(a[2]), "r"(a[3]), "r"(b[0]), "r"(b[1]));
}

__device__ __forceinline__ float sigmoid_fast(float x) {
    return __fdividef(1.0f, 1.0f + __expf(-x));
}

__device__ __forceinline__ float tanh_fast(float x) {
    x = fminf(fmaxf(x, -15.0f), 15.0f);
    float t = __expf(2.0f * x);
    return __fdividef(t - 1.0f, t + 1.0f);
}

// =====================================================================
// Generic GEMM: C[M,N] = A[M,K] * B[N,K]^T + bias[N]   (tf32 tensor cores)
// CTA tile 128x128, BK=32, 128 threads, warp grid 2x2 (warp tile 64x64).
// 2-stage cp.async double buffer (80 KB), 2 CTAs/SM.
// (Round-10 version — fastest measured GEMM.) M,N%128==0, K%64==0.
// =====================================================================
#define GST 40           // smem row stride in floats (mod 32 == 8, conflict-free)

__global__ __launch_bounds__(128, 2)
void gemm_tn(const float* __restrict__ A, const float* __restrict__ B,
             const float* __restrict__ bias, float* __restrict__ C,
             int M, int N, int K)
{
    extern __shared__ float gsm[];
    float* As = gsm;                         // [2][128][GST]
    float* Bs = gsm + 2 * 128 * GST;         // [2][128][GST]

    const int tid  = threadIdx.x;
    const int lane = tid & 31;
    const int warp = tid >> 5;
    const int wm   = (warp >> 1) * 64;   // warp grid 2 (M) x 2 (N)
    const int wn   = (warp & 1) * 64;
    const int gq   = lane >> 2;
    const int t4   = lane & 3;

    const int m0 = blockIdx.y * 128;
    const int n0 = blockIdx.x * 128;

    const int ld_row = tid >> 3;          // 0..15 (x8 strided covers 128 rows)
    const int ld_c4  = (tid & 7) * 4;

    const int nk = K / 32;

    auto issue = [&](int slot, int i) {
        const int kt = i * 32;
#pragma unroll
        for (int r = 0; r < 8; ++r) {
            int row = ld_row + 16 * r;
            const float* srcA = &A[(size_t)(m0 + row) * K + kt + ld_c4];
            const float* srcB = &B[(size_t)(n0 + row) * K + kt + ld_c4];
            unsigned dA = (unsigned)__cvta_generic_to_shared(
                &As[(slot * 128 + row) * GST + ld_c4]);
            unsigned dB = (unsigned)__cvta_generic_to_shared(
                &Bs[(slot * 128 + row) * GST + ld_c4]);
            asm volatile("cp.async.cg.shared.global [%0], [%1], 16;" :: "r"(dA), "l"(srcA));
            asm volatile("cp.async.cg.shared.global [%0], [%1], 16;" :: "r"(dB), "l"(srcB));
        }
        asm volatile("cp.async.commit_group;" ::: "memory");
    };

    float c[4][8][4];
#pragma unroll
    for (int i = 0; i < 4; ++i)
#pragma unroll
        for (int j = 0; j < 8; ++j)
#pragma unroll
            for (int r = 0; r < 4; ++r) c[i][j][r] = 0.0f;

    issue(0, 0);
    issue(1, 1);

    for (int i = 0; i < nk; ++i) {
        if (i + 1 < nk) asm volatile("cp.async.wait_group 1;" ::: "memory");
        else            asm volatile("cp.async.wait_group 0;" ::: "memory");
        __syncthreads();

        const float* as = As + (i & 1) * 128 * GST;
        const float* bs = Bs + (i & 1) * 128 * GST;
#pragma unroll
        for (int kk = 0; kk < 4; ++kk) {
            const int cc = kk * 8 + 2 * t4;
            unsigned a[4][4], b[8][2];
#pragma unroll
            for (int mi = 0; mi < 4; ++mi) {
                int r0 = wm + mi * 16 + gq;
                float2 x0 = *(const float2*)&as[r0 * GST + cc];
                float2 x1 = *(const float2*)&as[(r0 + 8) * GST + cc];
                a[mi][0] = f2tf(x0.x); a[mi][1] = f2tf(x1.x);
                a[mi][2] = f2tf(x0.y); a[mi][3] = f2tf(x1.y);
            }
#pragma unroll
            for (int ni = 0; ni < 8; ++ni) {
                float2 z = *(const float2*)&bs[(wn + ni * 8 + gq) * GST + cc];
                b[ni][0] = f2tf(z.x); b[ni][1] = f2tf(z.y);
            }
#pragma unroll
            for (int mi = 0; mi < 4; ++mi)
#pragma unroll
                for (int ni = 0; ni < 8; ++ni)
                    mma8(c[mi][ni], a[mi], b[ni]);
        }

        __syncthreads();
        if (i + 2 < nk) issue(i & 1, i + 2);
    }

    // epilogue: C = acc + bias
#pragma unroll
    for (int mi = 0; mi < 4; ++mi) {
#pragma unroll
        for (int ni = 0; ni < 8; ++ni) {
            int row = m0 + wm + mi * 16 + gq;
            int col = n0 + wn + ni * 8 + 2 * t4;
            float b0 = bias[col], b1 = bias[col + 1];
            float2 v0 = make_float2(c[mi][ni][0] + b0, c[mi][ni][1] + b1);
            float2 v1 = make_float2(c[mi][ni][2] + b0, c[mi][ni][3] + b1);
            *(float2*)&C[(size_t)row * N + col]       = v0;
            *(float2*)&C[(size_t)(row + 8) * N + col] = v1;
        }
    }
}

// =====================================================================
// Persistent GRU layer kernel — direct-L2 A, depth-8 register pipeline.
// grid = NCTA (128), 128 threads (4 warps, all consumers). CTA b owns
// hidden cols [b*8, b*8+8). Weight slice (24 x 1024) smem-resident tf32
// (row stride 1040: LDS.128-conflict-free).
// K processed as 64 pairs of 8-col groups; within a 16-col window,
// thread t4 owns cols {4t4..4t4+3} (same permutation for A and B, so
// the contraction is exact). A: 2 LDG.128/pair from L2 via a ring of 8
// pairs (issued ~400cyc ahead). B: 1 LDS.128 per gate per pair.
// No smem staging of A, no producers, no intra-step __syncthreads.
// =====================================================================
#define WST 1040         // weight smem row stride (mod 32 == 16)

__global__ __launch_bounds__(128, 1)
void gru_layer(const float* __restrict__ w_hh, const float* __restrict__ b_hh)
{
    extern __shared__ unsigned Bs[];                          // [24][WST]

    const int tid   = threadIdx.x;
    const int lane  = tid & 31;
    const int warp  = tid >> 5;          // 0..3, all consumers
    const int gq    = lane >> 2;
    const int t4    = lane & 3;
    const int r0    = warp * 16;         // M-tile rows
    const int j0    = blockIdx.x * JSL;
    const int jc    = j0 + 2 * t4;
    const int cj    = j0 >> 7;           // chunk counter owned by this CTA

    // ---- preload weight slice (24 x 1024) as tf32 ----
    for (int e = tid; e < 24 * 256; e += 128) {
        int row = e >> 8;
        int c4  = (e & 255) * 4;
        int gate = row >> 3, jj = row & 7;
        float4 v = *(const float4*)&w_hh[(size_t)(gate * HH + j0 + jj) * HH + c4];
        uint4 u; u.x = f2tf(v.x); u.y = f2tf(v.y); u.z = f2tf(v.z); u.w = f2tf(v.w);
        *(uint4*)&Bs[row * WST + c4] = u;
    }
    __syncthreads();

    // ---- hoist b_hh ----
    float2 bhr = *(const float2*)&b_hh[jc];
    float2 bhz = *(const float2*)&b_hh[HH + jc];
    float2 bhn = *(const float2*)&b_hh[2 * HH + jc];

    for (int t = 0; t < TT; ++t) {
        const float* h_in  = g_h + (size_t)(t & 1) * (BB * HH);
        float*       h_out = g_h + (size_t)((t + 1) & 1) * (BB * HH);
        const float* xg_t  = g_xg + (size_t)t * BB * G3;
        float*       y_t   = g_y  + (size_t)t * BB * HH;

        // ---- prefetch xg operands BEFORE the barrier (always ready) ----
        float2 xr0, xz0, xn0, xr1, xz1, xn1;
        {
            const float* xp0 = xg_t + (size_t)(r0 + gq) * G3 + jc;
            const float* xp1 = xg_t + (size_t)(r0 + gq + 8) * G3 + jc;
            xr0 = *(const float2*)(xp0);
            xz0 = *(const float2*)(xp0 + HH);
            xn0 = *(const float2*)(xp0 + 2 * HH);
            xr1 = *(const float2*)(xp1);
            xz1 = *(const float2*)(xp1 + HH);
            xn1 = *(const float2*)(xp1 + 2 * HH);
        }

        // ---- step barrier: wait for all 8 chunk groups of step t-1 ----
        if (tid < 8) {
            const unsigned tgt = 16u * (unsigned)t;
            const unsigned* fp = &g_flag[tid * 32];
            unsigned v;
            do {
                asm volatile("ld.acquire.gpu.global.u32 %0, [%1];" : "=r"(v) : "l"(fp));
            } while (v < tgt);
        }
        __syncthreads();

        // A-row base pointers: this thread's float4 within each 16-col window
        const float* ha = h_in + (r0 + gq) * HH + 4 * t4;
        const float* hb = ha + 8 * HH;
        float2 hold0 = *(const float2*)&h_in[(r0 + gq) * HH + jc];
        float2 hold1 = *(const float2*)&h_in[(r0 + gq + 8) * HH + jc];

        float acc[3][4];
#pragma unroll
        for (int ni = 0; ni < 3; ++ni)
#pragma unroll
            for (int r = 0; r < 4; ++r) acc[ni][r] = 0.0f;

        // ---- ring of 8 prefetched pairs (all indices compile-time) ----
        float4 rA[8], rB[8];
#pragma unroll
        for (int j = 0; j < 8; ++j) {
            rA[j] = *(const float4*)(ha + j * 16);
            rB[j] = *(const float4*)(hb + j * 16);
        }

        for (int g = 0; g < 8; ++g) {          // 8 groups x 8 pairs = 64 pairs
            const int pbase = g * 8;
#pragma unroll
            for (int j = 0; j < 8; ++j) {
                float4 cA = rA[j], cB = rB[j];
                if (g < 7) {                   // issue next group's loads early
                    rA[j] = *(const float4*)(ha + (pbase + 8 + j) * 16);
                    rB[j] = *(const float4*)(hb + (pbase + 8 + j) * 16);
                }
                const int col = (pbase + j) * 16 + 4 * t4;

                unsigned a0[4], a1[4];
                a0[0] = f2tf(cA.x); a0[1] = f2tf(cB.x);
                a0[2] = f2tf(cA.y); a0[3] = f2tf(cB.y);
                a1[0] = f2tf(cA.z); a1[1] = f2tf(cB.z);
                a1[2] = f2tf(cA.w); a1[3] = f2tf(cB.w);
#pragma unroll
                for (int ni = 0; ni < 3; ++ni) {
                    uint4 bb = *(const uint4*)&Bs[(ni * 8 + gq) * WST + col];
                    unsigned b0[2] = { bb.x, bb.y };
                    unsigned b1[2] = { bb.z, bb.w };
                    mma8(acc[ni], a0, b0);
                    mma8(acc[ni], a1, b1);
                }
            }
        }

        // ---- fused gate epilogue (accumulators complete; no reduction) ----
        {
            float r00 = sigmoid_fast(xr0.x + acc[0][0] + bhr.x);
            float r01 = sigmoid_fast(xr0.y + acc[0][1] + bhr.y);
            float r10 = sigmoid_fast(xr1.x + acc[0][2] + bhr.x);
            float r11 = sigmoid_fast(xr1.y + acc[0][3] + bhr.y);
            float z00 = sigmoid_fast(xz0.x + acc[1][0] + bhz.x);
            float z01 = sigmoid_fast(xz0.y + acc[1][1] + bhz.y);
            float z10 = sigmoid_fast(xz1.x + acc[1][2] + bhz.x);
            float z11 = sigmoid_fast(xz1.y + acc[1][3] + bhz.y);
            float n00 = tanh_fast(xn0.x + r00 * (acc[2][0] + bhn.x));
            float n01 = tanh_fast(xn0.y + r01 * (acc[2][1] + bhn.y));
            float n10 = tanh_fast(xn1.x + r10 * (acc[2][2] + bhn.x));
            float n11 = tanh_fast(xn1.y + r11 * (acc[2][3] + bhn.y));

            float2 o0 = make_float2((1.f - z00) * n00 + z00 * hold0.x,
                                    (1.f - z01) * n01 + z01 * hold0.y);
            float2 o1 = make_float2((1.f - z10) * n10 + z10 * hold1.x,
                                    (1.f - z11) * n11 + z11 * hold1.y);
            *(float2*)&h_out[(r0 + gq) * HH + jc]     = o0;
            *(float2*)&h_out[(r0 + gq + 8) * HH + jc] = o1;
            *(float2*)&y_t  [(r0 + gq) * HH + jc]     = o0;
            *(float2*)&y_t  [(r0 + gq + 8) * HH + jc] = o1;
        }

        // ---- publish: syncthreads gives happens-before; one release atomic ----
        __syncthreads();
        if (tid == 0) {
            asm volatile("red.release.gpu.global.add.u32 [%0], %1;"
                         :: "l"(&g_flag[cj * 32]), "r"(1u) : "memory");
        }
    }
}

// =====================================================================
// init hidden state (parity buffer 0) + reset producer flags
// =====================================================================
__global__ void copy_h(const float* __restrict__ src)
{
    int i = blockIdx.x * blockDim.x + threadIdx.x;
    if (i < BB * HH) g_h[i] = src[i];
    if (i < 8 * 32) g_flag[i] = 0;
}

// =====================================================================
// LayerNorm over last dim (1024), one block per row
// =====================================================================
__global__ __launch_bounds__(256)
void ln_kernel(const float* __restrict__ y, const float* __restrict__ gamma,
               const float* __restrict__ beta, float* __restrict__ out)
{
    __shared__ float sh[16];
    const size_t row = blockIdx.x;
    const int tid = threadIdx.x, lane = tid & 31, warp = tid >> 5;

    float4 v = ((const float4*)(y + row * HH))[tid];
    float s = v.x + v.y + v.z + v.w;
    float q = v.x * v.x + v.y * v.y + v.z * v.z + v.w * v.w;
#pragma unroll
    for (int o = 16; o > 0; o >>= 1) {
        s += __shfl_xor_sync(0xffffffffu, s, o);
        q += __shfl_xor_sync(0xffffffffu, q, o);
    }
    if (lane == 0) { sh[warp] = s; sh[8 + warp] = q; }
    __syncthreads();
    if (tid == 0) {
        float S = 0.0f, Q = 0.0f;
#pragma unroll
        for (int i = 0; i < 8; ++i) { S += sh[i]; Q += sh[8 + i]; }
        sh[0] = S; sh[8] = Q;
    }
    __syncthreads();
    const float mu   = sh[0] * (1.0f / HH);
    const float var  = sh[8] * (1.0f / HH) - mu * mu;
    const float rstd = rsqrtf(var + 1e-5f);

    float4 gm = ((const float4*)gamma)[tid];
    float4 bt = ((const float4*)beta)[tid];
    float4 o4;
    o4.x = (v.x - mu) * rstd * gm.x + bt.x;
    o4.y = (v.y - mu) * rstd * gm.y + bt.y;
    o4.z = (v.z - mu) * rstd * gm.z + bt.z;
    o4.w = (v.w - mu) * rstd * gm.w + bt.w;
    ((float4*)(out + row * HH))[tid] = o4;
}

// =====================================================================
// launcher  (8 graph nodes total)
// =====================================================================
extern "C" void kernel_launch(void* const* d_in, const int* in_sizes, int n_in,
                              void* d_out, int out_size)
{
    const float* x      = (const float*)d_in[0];
    const float* h      = (const float*)d_in[1];
    const float* w_ih0  = (const float*)d_in[2];
    const float* w_hh0  = (const float*)d_in[3];
    const float* b_ih0  = (const float*)d_in[4];
    const float* b_hh0  = (const float*)d_in[5];
    const float* w_ih1  = (const float*)d_in[6];
    const float* w_hh1  = (const float*)d_in[7];
    const float* b_ih1  = (const float*)d_in[8];
    const float* b_hh1  = (const float*)d_in[9];
    const float* ln_g   = (const float*)d_in[10];
    const float* ln_b   = (const float*)d_in[11];
    const float* ff_w   = (const float*)d_in[12];
    const float* ff_b   = (const float*)d_in[13];
    float* out = (float*)d_out;

    float* xg = nullptr;
    float* y  = nullptr;
    cudaGetSymbolAddress((void**)&xg, g_xg);
    cudaGetSymbolAddress((void**)&y,  g_y);

    const int smem_gru  = 24 * WST * 4;                // 99840 B
    const int smem_gemm = 2 * 2 * 128 * GST * 4;       // 81920 B (2 CTAs/SM)
    cudaFuncSetAttribute(gru_layer, cudaFuncAttributeMaxDynamicSharedMemorySize, smem_gru);
    cudaFuncSetAttribute(gemm_tn,   cudaFuncAttributeMaxDynamicSharedMemorySize, smem_gemm);

    // layer 0: input-side gate projections for all timesteps
    gemm_tn<<<dim3(G3 / 128, TBR / 128), 128, smem_gemm>>>(x, w_ih0, b_ih0, xg, TBR, G3, DIN);

    // layer 0 recurrence (persistent)
    copy_h<<<(BB * HH + 255) / 256, 256>>>(h);
    gru_layer<<<NCTA, 128, smem_gru>>>(w_hh0, b_hh0);

    // layer 1: input-side gate projections
    gemm_tn<<<dim3(G3 / 128, TBR / 128), 128, smem_gemm>>>(y, w_ih1, b_ih1, xg, TBR, G3, HH);

    // layer 1 recurrence (persistent)
    copy_h<<<(BB * HH + 255) / 256, 256>>>(h + BB * HH);
    gru_layer<<<NCTA, 128, smem_gru>>>(w_hh1, b_hh1);

    // LayerNorm (output reuses g_xg buffer)
    ln_kernel<<<TBR, 256>>>(y, ln_g, ln_b, xg);

    // output projection
    gemm_tn<<<dim3(DOUT / 128, TBR / 128), 128, smem_gemm>>>(xg, ff_w, ff_b, out, TBR, DOUT, HH);
}

// round 12
// speedup vs baseline: 1.8728x; 1.0083x over previous
#include <cuda_runtime.h>
#include <cstdint>

// ---------------- problem dims ----------------
#define TT   512
#define BB   64
#define DIN  512
#define HH   1024
#define G3   3072
#define DOUT 512
#define TBR  (TT*BB)     // 32768 rows

#define NCTA 128         // persistent kernel grid
#define JSL  8           // hidden columns per CTA (128*8 = 1024)

// ---------------- device scratch (no allocations allowed) ----------------
__device__ float g_xg [(size_t)TBR * G3];  // xg of current layer-in (reused as LN output)
__device__ float g_xg2[(size_t)TBR * G3];  // xg1 produced by fused layer-0 recurrence
__device__ float g_y [(size_t)TBR * HH];   // layer output sequence
__device__ float g_h [2 * BB * HH];        // ping-pong hidden state
__device__ unsigned g_flag[8 * 32];        // per-chunk producer counters (128B padded)

// ---------------- helpers ----------------
__device__ __forceinline__ unsigned f2tf(float x) {
    unsigned r;
    asm("cvt.rna.tf32.f32 %0, %1;" : "=r"(r) : "f"(x));
    return r;
}

__device__ __forceinline__ void mma8(float* c, const unsigned* a, const unsigned* b) {
    asm volatile(
        "mma.sync.aligned.m16n8k8.row.col.f32.tf32.tf32.f32 "
        "{%0,%1,%2,%3},{%4,%5,%6,%7},{%8,%9},{%0,%1,%2,%3};"
        : "+f"(c[0]), "+f"(c[1]), "+f"(c[2]), "+f"(c[3])
        : "r"(a[0]), "r"(a[1]), "r"(a[2]), "r"(a[3]), "r"(b[0]), "r"(b[1]));
}

__device__ __forceinline__ float sigmoid_fast(float x) {
    return __fdividef(1.0f, 1.0f + __expf(-x));
}

__device__ __forceinline__ float tanh_fast(float x) {
    x = fminf(fmaxf(x, -15.0f), 15.0f);
    float t = __expf(2.0f * x);
    return __fdividef(t - 1.0f, t + 1.0f);
}

// =====================================================================
// Generic GEMM: C[M,N] = A[M,K] * B[N,K]^T + bias[N]   (tf32 tensor cores)
// CTA tile 128x128, BK=32, 128 threads, warp grid 2x2 (warp tile 64x64).
// 2-stage cp.async double buffer (80 KB), 2 CTAs/SM.
// (Round-10 version — fastest measured GEMM.) M,N%128==0, K%64==0.
// =====================================================================
#define GST 40           // smem row stride in floats (mod 32 == 8, conflict-free)

__global__ __launch_bounds__(128, 2)
void gemm_tn(const float* __restrict__ A, const float* __restrict__ B,
             const float* __restrict__ bias, float* __restrict__ C,
             int M, int N, int K)
{
    extern __shared__ float gsm[];
    float* As = gsm;                         // [2][128][GST]
    float* Bs = gsm + 2 * 128 * GST;         // [2][128][GST]

    const int tid  = threadIdx.x;
    const int lane = tid & 31;
    const int warp = tid >> 5;
    const int wm   = (warp >> 1) * 64;   // warp grid 2 (M) x 2 (N)
    const int wn   = (warp & 1) * 64;
    const int gq   = lane >> 2;
    const int t4   = lane & 3;

    const int m0 = blockIdx.y * 128;
    const int n0 = blockIdx.x * 128;

    const int ld_row = tid >> 3;          // 0..15 (x8 strided covers 128 rows)
    const int ld_c4  = (tid & 7) * 4;

    const int nk = K / 32;

    auto issue = [&](int slot, int i) {
        const int kt = i * 32;
#pragma unroll
        for (int r = 0; r < 8; ++r) {
            int row = ld_row + 16 * r;
            const float* srcA = &A[(size_t)(m0 + row) * K + kt + ld_c4];
            const float* srcB = &B[(size_t)(n0 + row) * K + kt + ld_c4];
            unsigned dA = (unsigned)__cvta_generic_to_shared(
                &As[(slot * 128 + row) * GST + ld_c4]);
            unsigned dB = (unsigned)__cvta_generic_to_shared(
                &Bs[(slot * 128 + row) * GST + ld_c4]);
            asm volatile("cp.async.cg.shared.global [%0], [%1], 16;" :: "r"(dA), "l"(srcA));
            asm volatile("cp.async.cg.shared.global [%0], [%1], 16;" :: "r"(dB), "l"(srcB));
        }
        asm volatile("cp.async.commit_group;" ::: "memory");
    };

    float c[4][8][4];
#pragma unroll
    for (int i = 0; i < 4; ++i)
#pragma unroll
        for (int j = 0; j < 8; ++j)
#pragma unroll
            for (int r = 0; r < 4; ++r) c[i][j][r] = 0.0f;

    issue(0, 0);
    issue(1, 1);

    for (int i = 0; i < nk; ++i) {
        if (i + 1 < nk) asm volatile("cp.async.wait_group 1;" ::: "memory");
        else            asm volatile("cp.async.wait_group 0;" ::: "memory");
        __syncthreads();

        const float* as = As + (i & 1) * 128 * GST;
        const float* bs = Bs + (i & 1) * 128 * GST;
#pragma unroll
        for (int kk = 0; kk < 4; ++kk) {
            const int cc = kk * 8 + 2 * t4;
            unsigned a[4][4], b[8][2];
#pragma unroll
            for (int mi = 0; mi < 4; ++mi) {
                int r0 = wm + mi * 16 + gq;
                float2 x0 = *(const float2*)&as[r0 * GST + cc];
                float2 x1 = *(const float2*)&as[(r0 + 8) * GST + cc];
                a[mi][0] = f2tf(x0.x); a[mi][1] = f2tf(x1.x);
                a[mi][2] = f2tf(x0.y); a[mi][3] = f2tf(x1.y);
            }
#pragma unroll
            for (int ni = 0; ni < 8; ++ni) {
                float2 z = *(const float2*)&bs[(wn + ni * 8 + gq) * GST + cc];
                b[ni][0] = f2tf(z.x); b[ni][1] = f2tf(z.y);
            }
#pragma unroll
            for (int mi = 0; mi < 4; ++mi)
#pragma unroll
                for (int ni = 0; ni < 8; ++ni)
                    mma8(c[mi][ni], a[mi], b[ni]);
        }

        __syncthreads();
        if (i + 2 < nk) issue(i & 1, i + 2);
    }

    // epilogue: C = acc + bias
#pragma unroll
    for (int mi = 0; mi < 4; ++mi) {
#pragma unroll
        for (int ni = 0; ni < 8; ++ni) {
            int row = m0 + wm + mi * 16 + gq;
            int col = n0 + wn + ni * 8 + 2 * t4;
            float b0 = bias[col], b1 = bias[col + 1];
            float2 v0 = make_float2(c[mi][ni][0] + b0, c[mi][ni][1] + b1);
            float2 v1 = make_float2(c[mi][ni][2] + b0, c[mi][ni][3] + b1);
            *(float2*)&C[(size_t)row * N + col]       = v0;
            *(float2*)&C[(size_t)(row + 8) * N + col] = v1;
        }
    }
}

// =====================================================================
// Persistent GRU layer kernel — direct-L2 A, depth-8 register pipeline.
// FUSE=true additionally computes xg_next[t-1] = y_prev[t-1]*w_x^T + b_x
// from the SAME A fragments (h_in at step t IS y[t-1]) against 24 more
// smem-resident weight rows, writing to xg_out. Runs TT+1 steps: step
// TT does only the xg part for t-1 = TT-1; step 0 skips xg.
// =====================================================================
#define WST 1040         // weight smem row stride (mod 32 == 16)

template<bool FUSE>
__global__ __launch_bounds__(128, 1)
void gru_layer(const float* __restrict__ w_hh, const float* __restrict__ b_hh,
               const float* __restrict__ xg_in,
               const float* __restrict__ w_x,  const float* __restrict__ b_x,
               float* __restrict__ xg_out)
{
    extern __shared__ unsigned Bs[];                          // [24 or 48][WST]

    const int tid   = threadIdx.x;
    const int lane  = tid & 31;
    const int warp  = tid >> 5;          // 0..3, all consumers
    const int gq    = lane >> 2;
    const int t4    = lane & 3;
    const int r0    = warp * 16;         // M-tile rows
    const int j0    = blockIdx.x * JSL;
    const int jc    = j0 + 2 * t4;
    const int cj    = j0 >> 7;           // chunk counter owned by this CTA

    // ---- preload weight slices as tf32: rows 0-23 = w_hh, 24-47 = w_x ----
    const int nrows = FUSE ? 48 : 24;
    for (int e = tid; e < nrows * 256; e += 128) {
        int row = e >> 8;
        int c4  = (e & 255) * 4;
        const float* wsrc;
        if (row < 24) {
            int gate = row >> 3, jj = row & 7;
            wsrc = &w_hh[(size_t)(gate * HH + j0 + jj) * HH + c4];
        } else {
            int rx = row - 24;
            int gate = rx >> 3, jj = rx & 7;
            wsrc = &w_x[(size_t)(gate * HH + j0 + jj) * HH + c4];
        }
        float4 v = *(const float4*)wsrc;
        uint4 u; u.x = f2tf(v.x); u.y = f2tf(v.y); u.z = f2tf(v.z); u.w = f2tf(v.w);
        *(uint4*)&Bs[row * WST + c4] = u;
    }
    __syncthreads();

    // ---- hoist biases ----
    float2 bhr = *(const float2*)&b_hh[jc];
    float2 bhz = *(const float2*)&b_hh[HH + jc];
    float2 bhn = *(const float2*)&b_hh[2 * HH + jc];
    float2 bxr = make_float2(0.f, 0.f), bxz = bxr, bxn = bxr;
    if (FUSE) {
        bxr = *(const float2*)&b_x[jc];
        bxz = *(const float2*)&b_x[HH + jc];
        bxn = *(const float2*)&b_x[2 * HH + jc];
    }

    const int tend = FUSE ? (TT + 1) : TT;

    for (int t = 0; t < tend; ++t) {
        const bool do_hg = (t < TT);
        const bool do_xg = FUSE && (t >= 1);

        const float* h_in  = g_h + (size_t)(t & 1) * (BB * HH);
        float*       h_out = g_h + (size_t)((t + 1) & 1) * (BB * HH);
        const float* xgt   = xg_in + (size_t)t * BB * G3;
        float*       y_t   = g_y  + (size_t)t * BB * HH;

        // ---- prefetch xg_in operands BEFORE the barrier (always ready) ----
        float2 xr0, xz0, xn0, xr1, xz1, xn1;
        if (do_hg) {
            const float* xp0 = xgt + (size_t)(r0 + gq) * G3 + jc;
            const float* xp1 = xgt + (size_t)(r0 + gq + 8) * G3 + jc;
            xr0 = *(const float2*)(xp0);
            xz0 = *(const float2*)(xp0 + HH);
            xn0 = *(const float2*)(xp0 + 2 * HH);
            xr1 = *(const float2*)(xp1);
            xz1 = *(const float2*)(xp1 + HH);
            xn1 = *(const float2*)(xp1 + 2 * HH);
        }

        // ---- step barrier: wait for all 8 chunk groups of step t-1 ----
        if (tid < 8) {
            const unsigned tgt = 16u * (unsigned)t;
            const unsigned* fp = &g_flag[tid * 32];
            unsigned v;
            do {
                asm volatile("ld.acquire.gpu.global.u32 %0, [%1];" : "=r"(v) : "l"(fp));
            } while (v < tgt);
        }
        __syncthreads();

        // A-row base pointers: this thread's float4 within each 16-col window
        const float* ha = h_in + (r0 + gq) * HH + 4 * t4;
        const float* hb = ha + 8 * HH;
        float2 hold0 = *(const float2*)&h_in[(r0 + gq) * HH + jc];
        float2 hold1 = *(const float2*)&h_in[(r0 + gq + 8) * HH + jc];

        float acc[3][4], accx[3][4];
#pragma unroll
        for (int ni = 0; ni < 3; ++ni)
#pragma unroll
            for (int r = 0; r < 4; ++r) { acc[ni][r] = 0.0f; accx[ni][r] = 0.0f; }

        // ---- ring of 8 prefetched pairs (all indices compile-time) ----
        float4 rA[8], rB[8];
#pragma unroll
        for (int j = 0; j < 8; ++j) {
            rA[j] = *(const float4*)(ha + j * 16);
            rB[j] = *(const float4*)(hb + j * 16);
        }

        for (int g = 0; g < 8; ++g) {          // 8 groups x 8 pairs = 64 pairs
            const int pbase = g * 8;
#pragma unroll
            for (int j = 0; j < 8; ++j) {
                float4 cA = rA[j], cB = rB[j];
                if (g < 7) {                   // issue next group's loads early
                    rA[j] = *(const float4*)(ha + (pbase + 8 + j) * 16);
                    rB[j] = *(const float4*)(hb + (pbase + 8 + j) * 16);
                }
                const int col = (pbase + j) * 16 + 4 * t4;

                unsigned a0[4], a1[4];
                a0[0] = f2tf(cA.x); a0[1] = f2tf(cB.x);
                a0[2] = f2tf(cA.y); a0[3] = f2tf(cB.y);
                a1[0] = f2tf(cA.z); a1[1] = f2tf(cB.z);
                a1[2] = f2tf(cA.w); a1[3] = f2tf(cB.w);
#pragma unroll
                for (int ni = 0; ni < 3; ++ni) {
                    uint4 bb = *(const uint4*)&Bs[(ni * 8 + gq) * WST + col];
                    unsigned b0[2] = { bb.x, bb.y };
                    unsigned b1[2] = { bb.z, bb.w };
                    mma8(acc[ni], a0, b0);
                    mma8(acc[ni], a1, b1);
                    if (FUSE) {
                        uint4 bx = *(const uint4*)&Bs[((24 + ni * 8) + gq) * WST + col];
                        unsigned c0[2] = { bx.x, bx.y };
                        unsigned c1[2] = { bx.z, bx.w };
                        mma8(accx[ni], a0, c0);
                        mma8(accx[ni], a1, c1);
                    }
                }
            }
        }

        // ---- fused gate epilogue (hg) ----
        if (do_hg) {
            float r00 = sigmoid_fast(xr0.x + acc[0][0] + bhr.x);
            float r01 = sigmoid_fast(xr0.y + acc[0][1] + bhr.y);
            float r10 = sigmoid_fast(xr1.x + acc[0][2] + bhr.x);
            float r11 = sigmoid_fast(xr1.y + acc[0][3] + bhr.y);
            float z00 = sigmoid_fast(xz0.x + acc[1][0] + bhz.x);
            float z01 = sigmoid_fast(xz0.y + acc[1][1] + bhz.y);
            float z10 = sigmoid_fast(xz1.x + acc[1][2] + bhz.x);
            float z11 = sigmoid_fast(xz1.y + acc[1][3] + bhz.y);
            float n00 = tanh_fast(xn0.x + r00 * (acc[2][0] + bhn.x));
            float n01 = tanh_fast(xn0.y + r01 * (acc[2][1] + bhn.y));
            float n10 = tanh_fast(xn1.x + r10 * (acc[2][2] + bhn.x));
            float n11 = tanh_fast(xn1.y + r11 * (acc[2][3] + bhn.y));

            float2 o0 = make_float2((1.f - z00) * n00 + z00 * hold0.x,
                                    (1.f - z01) * n01 + z01 * hold0.y);
            float2 o1 = make_float2((1.f - z10) * n10 + z10 * hold1.x,
                                    (1.f - z11) * n11 + z11 * hold1.y);
            *(float2*)&h_out[(r0 + gq) * HH + jc]     = o0;
            *(float2*)&h_out[(r0 + gq + 8) * HH + jc] = o1;
            *(float2*)&y_t  [(r0 + gq) * HH + jc]     = o0;
            *(float2*)&y_t  [(r0 + gq + 8) * HH + jc] = o1;
        }

        // ---- publish (before the xg store: off the critical chain) ----
        __syncthreads();
        if (do_hg && tid == 0) {
            asm volatile("red.release.gpu.global.add.u32 [%0], %1;"
                         :: "l"(&g_flag[cj * 32]), "r"(1u) : "memory");
        }

        // ---- xg_next[t-1] store (consumed only by the next kernel) ----
        if (do_xg) {
            float* xo0 = xg_out + (size_t)(t - 1) * BB * G3 + (size_t)(r0 + gq) * G3;
            float* xo1 = xo0 + 8 * G3;
            float2 bx[3] = { bxr, bxz, bxn };
#pragma unroll
            for (int ni = 0; ni < 3; ++ni) {
                float2 v0 = make_float2(accx[ni][0] + bx[ni].x, accx[ni][1] + bx[ni].y);
                float2 v1 = make_float2(accx[ni][2] + bx[ni].x, accx[ni][3] + bx[ni].y);
                *(float2*)&xo0[ni * HH + jc] = v0;
                *(float2*)&xo1[ni * HH + jc] = v1;
            }
        }
    }
}

// =====================================================================
// init hidden state (parity buffer 0) + reset producer flags
// =====================================================================
__global__ void copy_h(const float* __restrict__ src)
{
    int i = blockIdx.x * blockDim.x + threadIdx.x;
    if (i < BB * HH) g_h[i] = src[i];
    if (i < 8 * 32) g_flag[i] = 0;
}

// =====================================================================
// LayerNorm over last dim (1024), one block per row
// =====================================================================
__global__ __launch_bounds__(256)
void ln_kernel(const float* __restrict__ y, const float* __restrict__ gamma,
               const float* __restrict__ beta, float* __restrict__ out)
{
    __shared__ float sh[16];
    const size_t row = blockIdx.x;
    const int tid = threadIdx.x, lane = tid & 31, warp = tid >> 5;

    float4 v = ((const float4*)(y + row * HH))[tid];
    float s = v.x + v.y + v.z + v.w;
    float q = v.x * v.x + v.y * v.y + v.z * v.z + v.w * v.w;
#pragma unroll
    for (int o = 16; o > 0; o >>= 1) {
        s += __shfl_xor_sync(0xffffffffu, s, o);
        q += __shfl_xor_sync(0xffffffffu, q, o);
    }
    if (lane == 0) { sh[warp] = s; sh[8 + warp] = q; }
    __syncthreads();
    if (tid == 0) {
        float S = 0.0f, Q = 0.0f;
#pragma unroll
        for (int i = 0; i < 8; ++i) { S += sh[i]; Q += sh[8 + i]; }
        sh[0] = S; sh[8] = Q;
    }
    __syncthreads();
    const float mu   = sh[0] * (1.0f / HH);
    const float var  = sh[8] * (1.0f / HH) - mu * mu;
    const float rstd = rsqrtf(var + 1e-5f);

    float4 gm = ((const float4*)gamma)[tid];
    float4 bt = ((const float4*)beta)[tid];
    float4 o4;
    o4.x = (v.x - mu) * rstd * gm.x + bt.x;
    o4.y = (v.y - mu) * rstd * gm.y + bt.y;
    o4.z = (v.z - mu) * rstd * gm.z + bt.z;
    o4.w = (v.w - mu) * rstd * gm.w + bt.w;
    ((float4*)(out + row * HH))[tid] = o4;
}

// =====================================================================
// launcher  (7 graph nodes total)
// =====================================================================
extern "C" void kernel_launch(void* const* d_in, const int* in_sizes, int n_in,
                              void* d_out, int out_size)
{
    const float* x      = (const float*)d_in[0];
    const float* h      = (const float*)d_in[1];
    const float* w_ih0  = (const float*)d_in[2];
    const float* w_hh0  = (const float*)d_in[3];
    const float* b_ih0  = (const float*)d_in[4];
    const float* b_hh0  = (const float*)d_in[5];
    const float* w_ih1  = (const float*)d_in[6];
    const float* w_hh1  = (const float*)d_in[7];
    const float* b_ih1  = (const float*)d_in[8];
    const float* b_hh1  = (const float*)d_in[9];
    const float* ln_g   = (const float*)d_in[10];
    const float* ln_b   = (const float*)d_in[11];
    const float* ff_w   = (const float*)d_in[12];
    const float* ff_b   = (const float*)d_in[13];
    float* out = (float*)d_out;

    float* xg = nullptr;
    float* xg2 = nullptr;
    float* y  = nullptr;
    cudaGetSymbolAddress((void**)&xg,  g_xg);
    cudaGetSymbolAddress((void**)&xg2, g_xg2);
    cudaGetSymbolAddress((void**)&y,   g_y);

    const int smem_gru0 = 48 * WST * 4;                // 199680 B (fused)
    const int smem_gru1 = 24 * WST * 4;                //  99840 B
    const int smem_gemm = 2 * 2 * 128 * GST * 4;       //  81920 B (2 CTAs/SM)
    cudaFuncSetAttribute(gru_layer<true>,  cudaFuncAttributeMaxDynamicSharedMemorySize, smem_gru0);
    cudaFuncSetAttribute(gru_layer<false>, cudaFuncAttributeMaxDynamicSharedMemorySize, smem_gru1);
    cudaFuncSetAttribute(gemm_tn,          cudaFuncAttributeMaxDynamicSharedMemorySize, smem_gemm);

    // layer 0: input-side gate projections for all timesteps
    gemm_tn<<<dim3(G3 / 128, TBR / 128), 128, smem_gemm>>>(x, w_ih0, b_ih0, xg, TBR, G3, DIN);

    // layer 0 recurrence (persistent, fused with xg1 = y0 * w_ih1^T + b_ih1)
    copy_h<<<(BB * HH + 255) / 256, 256>>>(h);
    gru_layer<true><<<NCTA, 128, smem_gru0>>>(w_hh0, b_hh0, xg, w_ih1, b_ih1, xg2);

    // layer 1 recurrence (persistent)
    copy_h<<<(BB * HH + 255) / 256, 256>>>(h + BB * HH);
    gru_layer<false><<<NCTA, 128, smem_gru1>>>(w_hh1, b_hh1, xg2, nullptr, nullptr, nullptr);

    // LayerNorm (output reuses g_xg buffer)
    ln_kernel<<<TBR, 256>>>(y, ln_g, ln_b, xg);

    // output projection
    gemm_tn<<<dim3(DOUT / 128, TBR / 128), 128, smem_gemm>>>(xg, ff_w, ff_b, out, TBR, DOUT, HH);
}

// round 16
// speedup vs baseline: 2.0464x; 1.0927x over previous
#include <cuda_runtime.h>
#include <cuda_fp16.h>
#include <cstdint>

// ---------------- problem dims ----------------
#define TT   512
#define BB   64
#define DIN  512
#define HH   1024
#define G3   3072
#define DOUT 512
#define TBR  (TT*BB)     // 32768 rows

#define NCTA 128         // persistent kernel grid
#define JSL  8           // hidden columns per CTA (128*8 = 1024)

// ---------------- device scratch (no allocations allowed) ----------------
__device__ float  g_xg[(size_t)TBR * G3];   // gate pre-activations (reused as LN output)
__device__ float  g_y [(size_t)TBR * HH];   // layer output sequence
__device__ float  g_h [2 * BB * HH];        // ping-pong hidden state (f32, exact hold path)
__device__ __half g_hh[2 * BB * HH];        // ping-pong hidden state (fp16 mma operand mirror)
__device__ unsigned g_flag[8 * 32];         // per-chunk producer counters (128B padded)

// ---------------- helpers ----------------
__device__ __forceinline__ unsigned h2pack(float a, float b) {
    __half2 t = __floats2half2_rn(a, b);
    return *(unsigned*)&t;
}

// mma.m16n8k16 f16 with f32 accumulators (same C layout as m16n8k8)
__device__ __forceinline__ void mma16(float* c, const unsigned* a, const unsigned* b) {
    asm volatile(
        "mma.sync.aligned.m16n8k16.row.col.f32.f16.f16.f32 "
        "{%0,%1,%2,%3},{%4,%5,%6,%7},{%8,%9},{%0,%1,%2,%3};"
        : "+f"(c[0]), "+f"(c[1]), "+f"(c[2]), "+f"(c[3])
        : "r"(a[0]), "r"(a[1]), "r"(a[2]), "r"(a[3]), "r"(b[0]), "r"(b[1]));
}

__device__ __forceinline__ float sigmoid_fast(float x) {
    return __fdividef(1.0f, 1.0f + __expf(-x));
}

__device__ __forceinline__ float tanh_fast(float x) {
    x = fminf(fmaxf(x, -15.0f), 15.0f);
    float t = __expf(2.0f * x);
    return __fdividef(t - 1.0f, t + 1.0f);
}

// =====================================================================
// Generic GEMM: C[M,N] = A[M,K] * B[N,K]^T + bias[N]   (fp16 tensor cores,
// f32 accumulate). CTA tile 128x128, BK=32, 128 threads, warp grid 2x2
// (warp tile 64x64), 2-stage cp.async f32 double buffer, consumer-side
// fp16 conversion. Fragment k-permutation: thread t4 owns phys cols
// {4t4..4t4+3} of each 16-col window on BOTH A and B (contraction exact).
// Requires M,N%128==0, K%64==0.
// =====================================================================
#define GST 48           // f32 smem row stride (mod 32 == 16 -> conflict-free LDS.128)
#define GSM (2 * 2 * 128 * GST * 4)   // 98304 B

__global__ __launch_bounds__(128, 2)
void gemm_tn(const float* __restrict__ A, const float* __restrict__ B,
             const float* __restrict__ bias, float* __restrict__ C,
             int M, int N, int K)
{
    extern __shared__ float gsm[];
    float* As = gsm;                         // [2][128][GST]
    float* Bs = gsm + 2 * 128 * GST;         // [2][128][GST]

    const int tid  = threadIdx.x;
    const int lane = tid & 31;
    const int warp = tid >> 5;
    const int wm   = (warp >> 1) * 64;   // warp grid 2 (M) x 2 (N)
    const int wn   = (warp & 1) * 64;
    const int gq   = lane >> 2;
    const int t4   = lane & 3;

    const int m0 = blockIdx.y * 128;
    const int n0 = blockIdx.x * 128;

    const int ld_row = tid >> 3;          // 0..15 (x8 strided covers 128 rows)
    const int ld_c4  = (tid & 7) * 4;

    const int nk = K / 32;

    auto issue = [&](int slot, int i) {
        const int kt = i * 32;
#pragma unroll
        for (int r = 0; r < 8; ++r) {
            int row = ld_row + 16 * r;
            const float* srcA = &A[(size_t)(m0 + row) * K + kt + ld_c4];
            const float* srcB = &B[(size_t)(n0 + row) * K + kt + ld_c4];
            unsigned dA = (unsigned)__cvta_generic_to_shared(
                &As[(slot * 128 + row) * GST + ld_c4]);
            unsigned dB = (unsigned)__cvta_generic_to_shared(
                &Bs[(slot * 128 + row) * GST + ld_c4]);
            asm volatile("cp.async.cg.shared.global [%0], [%1], 16;" :: "r"(dA), "l"(srcA));
            asm volatile("cp.async.cg.shared.global [%0], [%1], 16;" :: "r"(dB), "l"(srcB));
        }
        asm volatile("cp.async.commit_group;" ::: "memory");
    };

    float c[4][8][4];
#pragma unroll
    for (int i = 0; i < 4; ++i)
#pragma unroll
        for (int j = 0; j < 8; ++j)
#pragma unroll
            for (int r = 0; r < 4; ++r) c[i][j][r] = 0.0f;

    issue(0, 0);
    issue(1, 1);

    for (int i = 0; i < nk; ++i) {
        if (i + 1 < nk) asm volatile("cp.async.wait_group 1;" ::: "memory");
        else            asm volatile("cp.async.wait_group 0;" ::: "memory");
        __syncthreads();

        const float* as = As + (i & 1) * 128 * GST;
        const float* bs = Bs + (i & 1) * 128 * GST;
#pragma unroll
        for (int win = 0; win < 2; ++win) {            // two k16 windows per BK32
            const int cc = win * 16 + 4 * t4;          // phys cols 4t4..4t4+3
            unsigned a[4][4], b[8][2];
#pragma unroll
            for (int mi = 0; mi < 4; ++mi) {
                int r0 = wm + mi * 16 + gq;
                float4 x0 = *(const float4*)&as[r0 * GST + cc];
                float4 x1 = *(const float4*)&as[(r0 + 8) * GST + cc];
                a[mi][0] = h2pack(x0.x, x0.y);   // R0: row gq,   logical k {2t4,2t4+1}
                a[mi][1] = h2pack(x1.x, x1.y);   // R1: row gq+8
                a[mi][2] = h2pack(x0.z, x0.w);   // R2: row gq,   logical k {2t4+8,+9}
                a[mi][3] = h2pack(x1.z, x1.w);   // R3: row gq+8
            }
#pragma unroll
            for (int ni = 0; ni < 8; ++ni) {
                float4 z = *(const float4*)&bs[(wn + ni * 8 + gq) * GST + cc];
                b[ni][0] = h2pack(z.x, z.y);
                b[ni][1] = h2pack(z.z, z.w);
            }
#pragma unroll
            for (int mi = 0; mi < 4; ++mi)
#pragma unroll
                for (int ni = 0; ni < 8; ++ni)
                    mma16(c[mi][ni], a[mi], b[ni]);
        }

        __syncthreads();
        if (i + 2 < nk) issue(i & 1, i + 2);
    }

    // epilogue: C = acc + bias
#pragma unroll
    for (int mi = 0; mi < 4; ++mi) {
#pragma unroll
        for (int ni = 0; ni < 8; ++ni) {
            int row = m0 + wm + mi * 16 + gq;
            int col = n0 + wn + ni * 8 + 2 * t4;
            float b0 = bias[col], b1 = bias[col + 1];
            float2 v0 = make_float2(c[mi][ni][0] + b0, c[mi][ni][1] + b1);
            float2 v1 = make_float2(c[mi][ni][2] + b0, c[mi][ni][3] + b1);
            *(float2*)&C[(size_t)row * N + col]       = v0;
            *(float2*)&C[(size_t)(row + 8) * N + col] = v1;
        }
    }
}

// =====================================================================
// Persistent GRU layer kernel — fp16 operands, direct-L2 A stream.
// grid = NCTA (128), 128 threads (4 warps). CTA b owns hidden cols
// [b*8, b*8+8). Weight slice (24 x 1024) smem-resident as fp16.
// K = 64 windows of 16; per window: 2 LDG.64 (A rows from g_hh fp16
// mirror, ring of 8 windows prefetched), 3 LDS.64 (B gates), 3 mma16.
// h state kept in f32 (g_h) for the hold path; fp16 mirror (g_hh) only
// feeds the mma, matching tf32-class operand quantization.
// =====================================================================
#define WSTH 1040        // weight smem row stride in halfs (2080 B, conflict-free LDS.64)

__global__ __launch_bounds__(128, 1)
void gru_layer(const float* __restrict__ w_hh, const float* __restrict__ b_hh,
               const float* __restrict__ xg_in)
{
    extern __shared__ __half Bs[];                            // [24][WSTH]

    const int tid   = threadIdx.x;
    const int lane  = tid & 31;
    const int warp  = tid >> 5;
    const int gq    = lane >> 2;
    const int t4    = lane & 3;
    const int r0    = warp * 16;
    const int j0    = blockIdx.x * JSL;
    const int jc    = j0 + 2 * t4;
    const int cj    = j0 >> 7;

    // ---- preload weight slice (24 x 1024) as fp16 ----
    for (int e = tid; e < 24 * 128; e += 128) {    // 8 halfs per item
        int row = e >> 7;
        int c8  = (e & 127) * 8;
        int gate = row >> 3, jj = row & 7;
        const float* wsrc = &w_hh[(size_t)(gate * HH + j0 + jj) * HH + c8];
        float4 v0 = *(const float4*)(wsrc);
        float4 v1 = *(const float4*)(wsrc + 4);
        uint4 u;
        u.x = h2pack(v0.x, v0.y); u.y = h2pack(v0.z, v0.w);
        u.z = h2pack(v1.x, v1.y); u.w = h2pack(v1.z, v1.w);
        *(uint4*)&Bs[row * WSTH + c8] = u;
    }
    __syncthreads();

    float2 bhr = *(const float2*)&b_hh[jc];
    float2 bhz = *(const float2*)&b_hh[HH + jc];
    float2 bhn = *(const float2*)&b_hh[2 * HH + jc];

    for (int t = 0; t < TT; ++t) {
        const float*  h_in   = g_h  + (size_t)(t & 1) * (BB * HH);
        float*        h_out  = g_h  + (size_t)((t + 1) & 1) * (BB * HH);
        const __half* hh_in  = g_hh + (size_t)(t & 1) * (BB * HH);
        __half*       hh_out = g_hh + (size_t)((t + 1) & 1) * (BB * HH);
        const float*  xg_t   = xg_in + (size_t)t * BB * G3;
        float*        y_t    = g_y  + (size_t)t * BB * HH;

        // ---- prefetch xg operands BEFORE the barrier (always ready) ----
        float2 xr0, xz0, xn0, xr1, xz1, xn1;
        {
            const float* xp0 = xg_t + (size_t)(r0 + gq) * G3 + jc;
            const float* xp1 = xg_t + (size_t)(r0 + gq + 8) * G3 + jc;
            xr0 = *(const float2*)(xp0);
            xz0 = *(const float2*)(xp0 + HH);
            xn0 = *(const float2*)(xp0 + 2 * HH);
            xr1 = *(const float2*)(xp1);
            xz1 = *(const float2*)(xp1 + HH);
            xn1 = *(const float2*)(xp1 + 2 * HH);
        }

        // ---- step barrier: wait for all 8 chunk groups of step t-1 ----
        if (tid < 8) {
            const unsigned tgt = 16u * (unsigned)t;
            const unsigned* fp = &g_flag[tid * 32];
            unsigned v;
            do {
                asm volatile("ld.acquire.gpu.global.u32 %0, [%1];" : "=r"(v) : "l"(fp));
            } while (v < tgt);
        }
        __syncthreads();

        // A-row base pointers: this thread's 4 halfs within each 16-col window
        const __half* ha = hh_in + (r0 + gq) * HH + 4 * t4;
        const __half* hb = ha + 8 * HH;
        float2 hold0 = *(const float2*)&h_in[(r0 + gq) * HH + jc];
        float2 hold1 = *(const float2*)&h_in[(r0 + gq + 8) * HH + jc];

        float acc[3][4];
#pragma unroll
        for (int ni = 0; ni < 3; ++ni)
#pragma unroll
            for (int r = 0; r < 4; ++r) acc[ni][r] = 0.0f;

        // ---- ring of 8 prefetched windows ----
        uint2 rA[8], rB[8];
#pragma unroll
        for (int j = 0; j < 8; ++j) {
            rA[j] = *(const uint2*)(ha + j * 16);
            rB[j] = *(const uint2*)(hb + j * 16);
        }

        for (int g = 0; g < 8; ++g) {          // 8 groups x 8 windows = 64 windows
            const int wbase = g * 8;
#pragma unroll
            for (int j = 0; j < 8; ++j) {
                uint2 cA = rA[j], cB = rB[j];
                if (g < 7) {                   // prefetch next group's windows
                    rA[j] = *(const uint2*)(ha + (wbase + 8 + j) * 16);
                    rB[j] = *(const uint2*)(hb + (wbase + 8 + j) * 16);
                }
                const int col = (wbase + j) * 16 + 4 * t4;

                unsigned a[4];
                a[0] = cA.x;   // R0: row gq,   phys {4t4, 4t4+1}
                a[1] = cB.x;   // R1: row gq+8
                a[2] = cA.y;   // R2: row gq,   phys {4t4+2, 4t4+3}
                a[3] = cB.y;   // R3: row gq+8
#pragma unroll
                for (int ni = 0; ni < 3; ++ni) {
                    uint2 bb = *(const uint2*)&Bs[(ni * 8 + gq) * WSTH + col];
                    unsigned br[2] = { bb.x, bb.y };
                    mma16(acc[ni], a, br);
                }
            }
        }

        // ---- fused gate epilogue ----
        {
            float r00 = sigmoid_fast(xr0.x + acc[0][0] + bhr.x);
            float r01 = sigmoid_fast(xr0.y + acc[0][1] + bhr.y);
            float r10 = sigmoid_fast(xr1.x + acc[0][2] + bhr.x);
            float r11 = sigmoid_fast(xr1.y + acc[0][3] + bhr.y);
            float z00 = sigmoid_fast(xz0.x + acc[1][0] + bhz.x);
            float z01 = sigmoid_fast(xz0.y + acc[1][1] + bhz.y);
            float z10 = sigmoid_fast(xz1.x + acc[1][2] + bhz.x);
            float z11 = sigmoid_fast(xz1.y + acc[1][3] + bhz.y);
            float n00 = tanh_fast(xn0.x + r00 * (acc[2][0] + bhn.x));
            float n01 = tanh_fast(xn0.y + r01 * (acc[2][1] + bhn.y));
            float n10 = tanh_fast(xn1.x + r10 * (acc[2][2] + bhn.x));
            float n11 = tanh_fast(xn1.y + r11 * (acc[2][3] + bhn.y));

            float2 o0 = make_float2((1.f - z00) * n00 + z00 * hold0.x,
                                    (1.f - z01) * n01 + z01 * hold0.y);
            float2 o1 = make_float2((1.f - z10) * n10 + z10 * hold1.x,
                                    (1.f - z11) * n11 + z11 * hold1.y);
            *(float2*)&h_out[(r0 + gq) * HH + jc]     = o0;
            *(float2*)&h_out[(r0 + gq + 8) * HH + jc] = o1;
            *(float2*)&y_t  [(r0 + gq) * HH + jc]     = o0;
            *(float2*)&y_t  [(r0 + gq + 8) * HH + jc] = o1;
            // fp16 mirror for the next step's mma stream
            *(unsigned*)&hh_out[(r0 + gq) * HH + jc]     = h2pack(o0.x, o0.y);
            *(unsigned*)&hh_out[(r0 + gq + 8) * HH + jc] = h2pack(o1.x, o1.y);
        }

        // ---- publish: syncthreads gives happens-before; one release atomic ----
        __syncthreads();
        if (tid == 0) {
            asm volatile("red.release.gpu.global.add.u32 [%0], %1;"
                         :: "l"(&g_flag[cj * 32]), "r"(1u) : "memory");
        }
    }
}

// =====================================================================
// init hidden state (parity buffer 0, f32 + fp16 mirror) + reset flags
// =====================================================================
__global__ void copy_h(const float* __restrict__ src)
{
    int i = blockIdx.x * blockDim.x + threadIdx.x;
    if (i < BB * HH) {
        float v = src[i];
        g_h[i]  = v;
        g_hh[i] = __float2half_rn(v);
    }
    if (i < 8 * 32) g_flag[i] = 0;
}

// =====================================================================
// LayerNorm over last dim (1024), one block per row
// =====================================================================
__global__ __launch_bounds__(256)
void ln_kernel(const float* __restrict__ y, const float* __restrict__ gamma,
               const float* __restrict__ beta, float* __restrict__ out)
{
    __shared__ float sh[16];
    const size_t row = blockIdx.x;
    const int tid = threadIdx.x, lane = tid & 31, warp = tid >> 5;

    float4 v = ((const float4*)(y + row * HH))[tid];
    float s = v.x + v.y + v.z + v.w;
    float q = v.x * v.x + v.y * v.y + v.z * v.z + v.w * v.w;
#pragma unroll
    for (int o = 16; o > 0; o >>= 1) {
        s += __shfl_xor_sync(0xffffffffu, s, o);
        q += __shfl_xor_sync(0xffffffffu, q, o);
    }
    if (lane == 0) { sh[warp] = s; sh[8 + warp] = q; }
    __syncthreads();
    if (tid == 0) {
        float S = 0.0f, Q = 0.0f;
#pragma unroll
        for (int i = 0; i < 8; ++i) { S += sh[i]; Q += sh[8 + i]; }
        sh[0] = S; sh[8] = Q;
    }
    __syncthreads();
    const float mu   = sh[0] * (1.0f / HH);
    const float var  = sh[8] * (1.0f / HH) - mu * mu;
    const float rstd = rsqrtf(var + 1e-5f);

    float4 gm = ((const float4*)gamma)[tid];
    float4 bt = ((const float4*)beta)[tid];
    float4 o4;
    o4.x = (v.x - mu) * rstd * gm.x + bt.x;
    o4.y = (v.y - mu) * rstd * gm.y + bt.y;
    o4.z = (v.z - mu) * rstd * gm.z + bt.z;
    o4.w = (v.w - mu) * rstd * gm.w + bt.w;
    ((float4*)(out + row * HH))[tid] = o4;
}

// =====================================================================
// launcher  (8 graph nodes, single stream — no streams/events)
// =====================================================================
extern "C" void kernel_launch(void* const* d_in, const int* in_sizes, int n_in,
                              void* d_out, int out_size)
{
    const float* x      = (const float*)d_in[0];
    const float* h      = (const float*)d_in[1];
    const float* w_ih0  = (const float*)d_in[2];
    const float* w_hh0  = (const float*)d_in[3];
    const float* b_ih0  = (const float*)d_in[4];
    const float* b_hh0  = (const float*)d_in[5];
    const float* w_ih1  = (const float*)d_in[6];
    const float* w_hh1  = (const float*)d_in[7];
    const float* b_ih1  = (const float*)d_in[8];
    const float* b_hh1  = (const float*)d_in[9];
    const float* ln_g   = (const float*)d_in[10];
    const float* ln_b   = (const float*)d_in[11];
    const float* ff_w   = (const float*)d_in[12];
    const float* ff_b   = (const float*)d_in[13];
    float* out = (float*)d_out;

    float* xg = nullptr;
    float* y  = nullptr;
    cudaGetSymbolAddress((void**)&xg, g_xg);
    cudaGetSymbolAddress((void**)&y,  g_y);

    const int smem_gru = 24 * WSTH * 2;                // 49920 B (fp16 weights)
    cudaFuncSetAttribute(gru_layer, cudaFuncAttributeMaxDynamicSharedMemorySize, smem_gru);
    cudaFuncSetAttribute(gemm_tn,   cudaFuncAttributeMaxDynamicSharedMemorySize, GSM);

    // layer 0: xg0 = x * w_ih0^T + b_ih0   (K=512)
    gemm_tn<<<dim3(G3 / 128, TBR / 128), 128, GSM>>>(x, w_ih0, b_ih0, xg, TBR, G3, DIN);

    // layer 0 recurrence
    copy_h<<<(BB * HH + 255) / 256, 256>>>(h);
    gru_layer<<<NCTA, 128, smem_gru>>>(w_hh0, b_hh0, xg);

    // layer 1: xg1 = y0 * w_ih1^T + b_ih1  (K=1024)
    gemm_tn<<<dim3(G3 / 128, TBR / 128), 128, GSM>>>(y, w_ih1, b_ih1, xg, TBR, G3, HH);

    // layer 1 recurrence
    copy_h<<<(BB * HH + 255) / 256, 256>>>(h + BB * HH);
    gru_layer<<<NCTA, 128, smem_gru>>>(w_hh1, b_hh1, xg);

    // LayerNorm (output into g_xg)
    ln_kernel<<<TBR, 256>>>(y, ln_g, ln_b, xg);

    // output projection (K=1024)
    gemm_tn<<<dim3(DOUT / 128, TBR / 128), 128, GSM>>>(xg, ff_w, ff_b, out, TBR, DOUT, HH);
}